// round 12
// baseline (speedup 1.0000x reference)
#include <cuda_runtime.h>

// LIF neuron scan over time, fused across T in registers. FINAL (champion).
// x: [T=4, N] fp32, out: [T=4, N] fp32 binary spikes.
// u_t = u_{t-1}*DECAY + x_t ; s_t = (u_t > V_TH) ; u_t = s_t ? 0 : u_t
//
// Memory-wall kernel: 205.5 MB read + 205.5 MB written, zero reuse -> 411 MB
// hard traffic floor. Runs at 6.22-6.24 TB/s = the B300 LTS chip cap
// (~6300 B/cyc, path-independent; a TMA rewrite hits the same ceiling).
// Falsified levers (R1-R10): per-thread MLP>4 (occupancy loss), persistent
// grid (load serialization), ld/st cache policies (no-reuse stream),
// block sizes {128,256,512}, bounds-guard elision. Run-to-run container
// noise (+-4us kernel-side on identical binaries) exceeds all residual
// structural deltas -> session converged at the roofline.
//
// Structure: flat launch, 256 thr/CTA (8 CTAs/SM, 64 warps), one float4 lane
// per thread, all 4 timestep loads front-batched (4x LDG.128, MLP=4),
// streaming stores (STG.128 evict-first).

#define LIF_DECAY 0.25f
#define LIF_VTH   1.0f
#define LIF_THREADS 256

#define LIF_STEP(XT)                                               \
    do {                                                           \
        u.x = fmaf(u.x, LIF_DECAY, (XT).x);                        \
        u.y = fmaf(u.y, LIF_DECAY, (XT).y);                        \
        u.z = fmaf(u.z, LIF_DECAY, (XT).z);                        \
        u.w = fmaf(u.w, LIF_DECAY, (XT).w);                        \
        s.x = (u.x > LIF_VTH) ? 1.0f : 0.0f;                       \
        s.y = (u.y > LIF_VTH) ? 1.0f : 0.0f;                       \
        s.z = (u.z > LIF_VTH) ? 1.0f : 0.0f;                       \
        s.w = (u.w > LIF_VTH) ? 1.0f : 0.0f;                       \
        u.x = fmaf(-s.x, u.x, u.x);                                \
        u.y = fmaf(-s.y, u.y, u.y);                                \
        u.z = fmaf(-s.z, u.z, u.z);                                \
        u.w = fmaf(-s.w, u.w, u.w);                                \
    } while (0)

#define LIF_BODY(GUARD)                                            \
    int i = blockIdx.x * LIF_THREADS + threadIdx.x;                \
    GUARD                                                          \
    float4 x0 = x[i];                                              \
    float4 x1 = x[n4 + i];                                         \
    float4 x2 = x[2 * n4 + i];                                     \
    float4 x3 = x[3 * n4 + i];                                     \
    float4 u = make_float4(0.f, 0.f, 0.f, 0.f);                    \
    float4 s;                                                      \
    LIF_STEP(x0); __stcs(&out[i],          s);                     \
    LIF_STEP(x1); __stcs(&out[n4 + i],     s);                     \
    LIF_STEP(x2); __stcs(&out[2 * n4 + i], s);                     \
    LIF_STEP(x3); __stcs(&out[3 * n4 + i], s);

__global__ __launch_bounds__(LIF_THREADS, 8) void lif_kernel_exact(
    const float4* __restrict__ x, float4* __restrict__ out, int n4)
{
    LIF_BODY(/* no guard: grid * block == n4 */)
}

__global__ __launch_bounds__(LIF_THREADS, 8) void lif_kernel_guarded(
    const float4* __restrict__ x, float4* __restrict__ out, int n4)
{
    LIF_BODY(if (i >= n4) return;)
}

extern "C" void kernel_launch(void* const* d_in, const int* in_sizes, int n_in,
                              void* d_out, int out_size)
{
    const float* x = (const float*)d_in[0];
    float* out = (float*)d_out;

    int total = in_sizes[0];      // T * N
    int n = total / 4;            // elements per timestep (T = 4)
    int n4 = n / 4;               // float4 lanes per timestep

    if ((n4 % LIF_THREADS) == 0) {
        lif_kernel_exact<<<n4 / LIF_THREADS, LIF_THREADS>>>(
            (const float4*)x, (float4*)out, n4);
    } else {
        lif_kernel_guarded<<<(n4 + LIF_THREADS - 1) / LIF_THREADS, LIF_THREADS>>>(
            (const float4*)x, (float4*)out, n4);
    }
}

// round 13
// speedup vs baseline: 1.0360x; 1.0360x over previous
#include <cuda_runtime.h>

// LIF neuron scan over time, fused across T in registers. FINAL (champion).
// x: [T=4, N] fp32, out: [T=4, N] fp32 binary spikes.
// u_t = u_{t-1}*DECAY + x_t ; s_t = (u_t > V_TH) ; u_t = s_t ? 0 : u_t
//
// Memory-wall kernel: 205.5 MB read + 205.5 MB written, zero reuse -> 411 MB
// hard traffic floor. Nominal runs: 57.3us kernel at 6.22-6.24 TB/s = the
// B300 LTS chip cap (~6300 B/cyc, path-independent; TMA hits the same wall).
// Falsified levers (R1-R11): per-thread MLP>4, persistent grid, ld/st cache
// policies, block sizes {128,256,512}, guard elision. Identical binaries
// measure bimodally (57.3 vs ~61.2us) across container holds -> pool
// clock-state noise, not code. Session converged at the roofline.
//
// Structure: flat launch, 256 thr/CTA (8 CTAs/SM, 64 warps), one float4 lane
// per thread, all 4 timestep loads front-batched (4x LDG.128, MLP=4),
// streaming stores (STG.128 evict-first).

#define LIF_DECAY 0.25f
#define LIF_VTH   1.0f
#define LIF_THREADS 256

#define LIF_STEP(XT)                                               \
    do {                                                           \
        u.x = fmaf(u.x, LIF_DECAY, (XT).x);                        \
        u.y = fmaf(u.y, LIF_DECAY, (XT).y);                        \
        u.z = fmaf(u.z, LIF_DECAY, (XT).z);                        \
        u.w = fmaf(u.w, LIF_DECAY, (XT).w);                        \
        s.x = (u.x > LIF_VTH) ? 1.0f : 0.0f;                       \
        s.y = (u.y > LIF_VTH) ? 1.0f : 0.0f;                       \
        s.z = (u.z > LIF_VTH) ? 1.0f : 0.0f;                       \
        s.w = (u.w > LIF_VTH) ? 1.0f : 0.0f;                       \
        u.x = fmaf(-s.x, u.x, u.x);                                \
        u.y = fmaf(-s.y, u.y, u.y);                                \
        u.z = fmaf(-s.z, u.z, u.z);                                \
        u.w = fmaf(-s.w, u.w, u.w);                                \
    } while (0)

#define LIF_BODY(GUARD)                                            \
    int i = blockIdx.x * LIF_THREADS + threadIdx.x;                \
    GUARD                                                          \
    float4 x0 = x[i];                                              \
    float4 x1 = x[n4 + i];                                         \
    float4 x2 = x[2 * n4 + i];                                     \
    float4 x3 = x[3 * n4 + i];                                     \
    float4 u = make_float4(0.f, 0.f, 0.f, 0.f);                    \
    float4 s;                                                      \
    LIF_STEP(x0); __stcs(&out[i],          s);                     \
    LIF_STEP(x1); __stcs(&out[n4 + i],     s);                     \
    LIF_STEP(x2); __stcs(&out[2 * n4 + i], s);                     \
    LIF_STEP(x3); __stcs(&out[3 * n4 + i], s);

__global__ __launch_bounds__(LIF_THREADS, 8) void lif_kernel_exact(
    const float4* __restrict__ x, float4* __restrict__ out, int n4)
{
    LIF_BODY(/* no guard: grid * block == n4 */)
}

__global__ __launch_bounds__(LIF_THREADS, 8) void lif_kernel_guarded(
    const float4* __restrict__ x, float4* __restrict__ out, int n4)
{
    LIF_BODY(if (i >= n4) return;)
}

extern "C" void kernel_launch(void* const* d_in, const int* in_sizes, int n_in,
                              void* d_out, int out_size)
{
    const float* x = (const float*)d_in[0];
    float* out = (float*)d_out;

    int total = in_sizes[0];      // T * N
    int n = total / 4;            // elements per timestep (T = 4)
    int n4 = n / 4;               // float4 lanes per timestep

    if ((n4 % LIF_THREADS) == 0) {
        lif_kernel_exact<<<n4 / LIF_THREADS, LIF_THREADS>>>(
            (const float4*)x, (float4*)out, n4);
    } else {
        lif_kernel_guarded<<<(n4 + LIF_THREADS - 1) / LIF_THREADS, LIF_THREADS>>>(
            (const float4*)x, (float4*)out, n4);
    }
}